// round 1
// baseline (speedup 1.0000x reference)
#include <cuda_runtime.h>
#include <cuda_bf16.h>
#include <math.h>

// Problem constants
constexpr int B_  = 8;
constexpr int P_  = 196;    // 14*14 pixels
constexpr int T_  = 64;
constexpr int H_  = 768;    // HIDDEN_DIM
constexpr int MD  = 2048;   // MAP_DIM
constexpr int BP  = B_ * P_;   // 1568
constexpr int BT  = B_ * T_;   // 512

// Scratch (device globals: no allocation allowed)
__device__ float g_mlo[BP * H_];     // 4.8 MB : map_linear output (bias-preinit, atomic-accum)
__device__ float g_ctx[BT * MD];     // 4.0 MB : context vectors
__device__ float g_attn[BT * P_];    // fallback attn storage if d_out has no room

// ---------------------------------------------------------------------------
// f32x2 packed-FMA helpers (sm_100+ PTX)
// ---------------------------------------------------------------------------
__device__ __forceinline__ unsigned long long splat2(float x) {
    unsigned long long r;
    asm("mov.b64 %0, {%1, %1};" : "=l"(r) : "f"(x));
    return r;
}
__device__ __forceinline__ unsigned long long ffma2(unsigned long long a,
                                                    unsigned long long b,
                                                    unsigned long long c) {
    unsigned long long d;
    asm("fma.rn.f32x2 %0, %1, %2, %3;" : "=l"(d) : "l"(a), "l"(b), "l"(c));
    return d;
}
__device__ __forceinline__ float2 unpack2(unsigned long long v) {
    float2 f;
    asm("mov.b64 {%0, %1}, %2;" : "=f"(f.x), "=f"(f.y) : "l"(v));
    return f;
}

// ---------------------------------------------------------------------------
// Generic TN GEMM with split-K atomic epilogue:
//   C[m,n] += sum_{k in chunk} A[m,k] * W[n,k]
// A: M x K row-major.  W: N x K row-major.  C must be pre-initialized (bias etc).
// BM=BN=64, BK=16, TM=TN=8, 64 threads. f32x2 packed accumulators over n-pairs.
// ---------------------------------------------------------------------------
template<int BM, int BN, int BK, int TM, int TN>
__global__ void __launch_bounds__(64, 8)
gemm_tn_atomic(const float* __restrict__ A, const float* __restrict__ W,
               float* __restrict__ C, int M, int N, int K, int kChunk)
{
    constexpr int NT = (BM / TM) * (BN / TN);   // 64 threads
    __shared__ float As[BK][BM];
    __shared__ float Bs[BK][BN];

    const int tid = threadIdx.x;
    const int m0  = blockIdx.x * BM;
    const int n0  = blockIdx.y * BN;
    const int k0  = blockIdx.z * kChunk;

    const int tx = tid % (BN / TN);         // 0..7
    const int ty = tid / (BN / TN);         // 0..7
    const int rowBase = ty * TM;
    const int colBase = tx * TN;

    unsigned long long acc[TM][TN / 2];
    #pragma unroll
    for (int i = 0; i < TM; i++)
        #pragma unroll
        for (int j = 0; j < TN / 2; j++) acc[i][j] = 0ull;   // bits of {0.f,0.f}

    for (int kt = k0; kt < k0 + kChunk; kt += BK) {
        // ---- stage A tile (BM x BK) ----
        #pragma unroll
        for (int l = 0; l < (BM * BK / 4) / NT; l++) {       // 4 float4 per thread
            int idx = tid + l * NT;
            int r = idx / (BK / 4);
            int c = idx % (BK / 4);
            float4 v = make_float4(0.f, 0.f, 0.f, 0.f);
            if (m0 + r < M)
                v = *(const float4*)(A + (size_t)(m0 + r) * K + kt + 4 * c);
            As[4 * c + 0][r] = v.x;
            As[4 * c + 1][r] = v.y;
            As[4 * c + 2][r] = v.z;
            As[4 * c + 3][r] = v.w;
        }
        // ---- stage W tile (BN x BK); N,K always tile-aligned here ----
        #pragma unroll
        for (int l = 0; l < (BN * BK / 4) / NT; l++) {
            int idx = tid + l * NT;
            int r = idx / (BK / 4);
            int c = idx % (BK / 4);
            float4 v = *(const float4*)(W + (size_t)(n0 + r) * K + kt + 4 * c);
            Bs[4 * c + 0][r] = v.x;
            Bs[4 * c + 1][r] = v.y;
            Bs[4 * c + 2][r] = v.z;
            Bs[4 * c + 3][r] = v.w;
        }
        __syncthreads();

        #pragma unroll
        for (int k = 0; k < BK; k++) {
            float a[TM];
            *(float4*)&a[0] = *(const float4*)&As[k][rowBase];
            *(float4*)&a[4] = *(const float4*)&As[k][rowBase + 4];
            unsigned long long b[TN / 2];
            #pragma unroll
            for (int j = 0; j < TN / 2; j++)
                b[j] = *(const unsigned long long*)&Bs[k][colBase + 2 * j];
            #pragma unroll
            for (int i = 0; i < TM; i++) {
                unsigned long long av = splat2(a[i]);
                #pragma unroll
                for (int j = 0; j < TN / 2; j++)
                    acc[i][j] = ffma2(av, b[j], acc[i][j]);
            }
        }
        __syncthreads();
    }

    // ---- split-K atomic epilogue ----
    #pragma unroll
    for (int i = 0; i < TM; i++) {
        int row = m0 + rowBase + i;
        if (row >= M) continue;
        float* cp = C + (size_t)row * N + n0 + colBase;
        #pragma unroll
        for (int j = 0; j < TN / 2; j++) {
            float2 v = unpack2(acc[i][j]);
            atomicAdd(cp + 2 * j + 0, v.x);
            atomicAdd(cp + 2 * j + 1, v.y);
        }
    }
}

// ---------------------------------------------------------------------------
// C pre-initializers
// ---------------------------------------------------------------------------
__global__ void init_mlo_kernel(float* __restrict__ mlo, const float* __restrict__ b_map)
{
    int i = blockIdx.x * 256 + threadIdx.x;
    if (i < BP * H_) mlo[i] = b_map[i % H_];
}

__global__ void init_out_kernel(float* __restrict__ out, const float* __restrict__ b_final,
                                const float* __restrict__ hiddens)
{
    int i = blockIdx.x * 256 + threadIdx.x;
    if (i < BT * H_) out[i] = b_final[i % H_] + hiddens[i];
}

// ---------------------------------------------------------------------------
// scores + softmax:
//   score[b,t,p] = sum_h relu(mlo[b,p,h] + hid[b,t,h]) * wr[h]   (+b_rect: softmax-invariant)
//   attn[b,t,:]  = softmax over p
// Block = (b, group of 4 t's), 256 threads (8 warps). Warps stride over p;
// each lane keeps 4 t-accumulators while streaming one mlo row.
// ---------------------------------------------------------------------------
__global__ void __launch_bounds__(256)
scores_softmax_kernel(const float* __restrict__ mlo, const float* __restrict__ hiddens,
                      const float* __restrict__ W_rect, float* __restrict__ attn_out)
{
    constexpr int TG = 4;
    __shared__ __align__(16) float s_wr[H_];
    __shared__ __align__(16) float s_hid[TG][H_];
    __shared__ float s_sc[TG][P_];

    const int b  = blockIdx.y;
    const int t0 = blockIdx.x * TG;
    const int tid = threadIdx.x;

    for (int i = tid; i < H_; i += 256) s_wr[i] = W_rect[i];
    for (int i = tid; i < TG * H_; i += 256) {
        int j = i / H_, h = i % H_;
        s_hid[j][h] = hiddens[(size_t)(b * T_ + t0 + j) * H_ + h];
    }
    __syncthreads();

    const int warp = tid >> 5;
    const int lane = tid & 31;

    for (int p = warp; p < P_; p += 8) {
        const float4* mrow = (const float4*)(mlo + (size_t)(b * P_ + p) * H_);
        float acc[TG] = {0.f, 0.f, 0.f, 0.f};
        #pragma unroll
        for (int q = lane; q < H_ / 4; q += 32) {     // 6 iterations
            float4 x = mrow[q];
            float4 w = ((const float4*)s_wr)[q];
            #pragma unroll
            for (int j = 0; j < TG; j++) {
                float4 hd = ((const float4*)s_hid[j])[q];
                acc[j] += fmaxf(x.x + hd.x, 0.f) * w.x
                        + fmaxf(x.y + hd.y, 0.f) * w.y
                        + fmaxf(x.z + hd.z, 0.f) * w.z
                        + fmaxf(x.w + hd.w, 0.f) * w.w;
            }
        }
        #pragma unroll
        for (int j = 0; j < TG; j++) {
            float v = acc[j];
            #pragma unroll
            for (int o = 16; o > 0; o >>= 1) v += __shfl_xor_sync(0xffffffffu, v, o);
            if (lane == 0) s_sc[j][p] = v;
        }
    }
    __syncthreads();

    if (warp < TG) {
        const int j = warp;
        float mx = -1e30f;
        for (int p = lane; p < P_; p += 32) mx = fmaxf(mx, s_sc[j][p]);
        #pragma unroll
        for (int o = 16; o > 0; o >>= 1) mx = fmaxf(mx, __shfl_xor_sync(0xffffffffu, mx, o));
        float sm = 0.f;
        for (int p = lane; p < P_; p += 32) {
            float e = expf(s_sc[j][p] - mx);
            s_sc[j][p] = e;
            sm += e;
        }
        #pragma unroll
        for (int o = 16; o > 0; o >>= 1) sm += __shfl_xor_sync(0xffffffffu, sm, o);
        float inv = 1.f / sm;
        float* ap = attn_out + (size_t)(b * T_ + t0 + j) * P_;
        for (int p = lane; p < P_; p += 32) ap[p] = s_sc[j][p] * inv;
    }
}

// ---------------------------------------------------------------------------
// ctx[b,t,m] = sum_p attn[b,t,p] * fm[b,p,m]
// Block = (128 m-cols, 32 t-rows, b). 256 threads; attn tile in smem (25 KB).
// ---------------------------------------------------------------------------
__global__ void __launch_bounds__(256)
ctx_kernel(const float* __restrict__ attn, const float* __restrict__ fm,
           float* __restrict__ ctx)
{
    __shared__ float s_at[32][P_];
    const int m0 = blockIdx.x * 128;
    const int tg = blockIdx.y;          // 0..1 (t-groups of 32)
    const int b  = blockIdx.z;
    const int tid = threadIdx.x;
    const int tx = tid & 31;            // m group (4 cols)
    const int ty = tid >> 5;            // 0..7 -> 4 t each

    for (int i = tid; i < 32 * P_; i += 256)
        s_at[i / P_][i % P_] = attn[(size_t)(b * T_ + tg * 32 + i / P_) * P_ + i % P_];
    __syncthreads();

    float acc[4][4] = {};
    const float* fmb = fm + (size_t)b * P_ * MD + m0 + tx * 4;
    #pragma unroll 4
    for (int p = 0; p < P_; p++) {
        float4 f = *(const float4*)(fmb + (size_t)p * MD);
        #pragma unroll
        for (int i = 0; i < 4; i++) {
            float a = s_at[ty * 4 + i][p];
            acc[i][0] += a * f.x;
            acc[i][1] += a * f.y;
            acc[i][2] += a * f.z;
            acc[i][3] += a * f.w;
        }
    }
    #pragma unroll
    for (int i = 0; i < 4; i++) {
        float* cp = ctx + (size_t)(b * T_ + tg * 32 + ty * 4 + i) * MD + m0 + tx * 4;
        *(float4*)cp = make_float4(acc[i][0], acc[i][1], acc[i][2], acc[i][3]);
    }
}

// ---------------------------------------------------------------------------
// launch
// ---------------------------------------------------------------------------
extern "C" void kernel_launch(void* const* d_in, const int* in_sizes, int n_in,
                              void* d_out, int out_size)
{
    const float* maps    = (const float*)d_in[0];   // (8,14,14,2048) == (BP, MD)
    const float* hiddens = (const float*)d_in[1];   // (8,64,768)     == (BT, H)
    const float* W_map   = (const float*)d_in[2];   // (768, 2048)
    const float* b_map   = (const float*)d_in[3];   // (768,)
    const float* W_final = (const float*)d_in[4];   // (768, 2048)
    const float* b_final = (const float*)d_in[5];   // (768,)
    const float* W_rect  = (const float*)d_in[6];   // (1, 768)
    // d_in[7] = b_rect : softmax-invariant, unused.

    float* out = (float*)d_out;                     // [out (BT,H) | attn (BT,P)]

    void *p_mlo_v, *p_ctx_v, *p_attn_v;
    cudaGetSymbolAddress(&p_mlo_v,  g_mlo);
    cudaGetSymbolAddress(&p_ctx_v,  g_ctx);
    cudaGetSymbolAddress(&p_attn_v, g_attn);
    float* p_mlo = (float*)p_mlo_v;
    float* p_ctx = (float*)p_ctx_v;

    // If d_out can hold both tensors, attn lives right after `out`.
    float* attn = (out_size >= BT * H_ + BT * P_) ? out + (size_t)BT * H_
                                                  : (float*)p_attn_v;

    // 1. mlo = b_map (broadcast)
    init_mlo_kernel<<<(BP * H_ + 255) / 256, 256>>>(p_mlo, b_map);

    // 2. mlo += fm @ W_map^T    (split-K=2)
    gemm_tn_atomic<64, 64, 16, 8, 8>
        <<<dim3((BP + 63) / 64, H_ / 64, 2), 64>>>(maps, W_map, p_mlo,
                                                   BP, H_, MD, MD / 2);

    // 3. scores + softmax -> attn
    scores_softmax_kernel<<<dim3(T_ / 4, B_), 256>>>(p_mlo, hiddens, W_rect, attn);

    // 4. ctx = attn @ fm (per batch)
    ctx_kernel<<<dim3(MD / 128, 2, B_), 256>>>(attn, maps, p_ctx);

    // 5. out = b_final + hiddens
    init_out_kernel<<<(BT * H_ + 255) / 256, 256>>>(out, b_final, hiddens);

    // 6. out += ctx @ W_final^T  (split-K=4)
    gemm_tn_atomic<64, 64, 16, 8, 8>
        <<<dim3(BT / 64, H_ / 64, 4), 64>>>(p_ctx, W_final, out,
                                            BT, H_, MD, MD / 4);
}